// round 1
// baseline (speedup 1.0000x reference)
#include <cuda_runtime.h>

#define NT 100000
#define NC 100000
#define NE 1600000
#define NP 200000
#define HD 128

// ---- scratch (static __device__, no allocation) ----
__device__ float g_dis_t[NT];     // truck deg -> dis
__device__ float g_dis_c[NC];     // car deg -> dis
__device__ float g_coef[NT];      // truck scalar aggregate
__device__ float g_gc[NC * 3];    // car 3-dim aggregate
__device__ float4 g_u[NT + NC];   // per-node compact coefficients
__device__ float g_M[36];         // 6x6 quadratic-form matrix

// ---- k0: zero scratch ----
__global__ void k_zero() {
    int i = blockIdx.x * blockDim.x + threadIdx.x;
    if (i < NT) { g_dis_t[i] = 0.f; g_coef[i] = 0.f; }
    if (i < NC) g_dis_c[i] = 0.f;
    if (i < NC * 3) g_gc[i] = 0.f;
}

// ---- k1: degree accumulation (both graphs in one pass) ----
__global__ void k_deg(const int* __restrict__ eit,
                      const int* __restrict__ eic,
                      const float* __restrict__ ew) {
    int e = blockIdx.x * blockDim.x + threadIdx.x;
    if (e >= NE) return;
    atomicAdd(&g_dis_t[eit[NE + e]], 1.0f);
    atomicAdd(&g_dis_c[eic[NE + e]], ew[e]);
}

// ---- k2: deg -> dis = rsqrt(deg + 1) ----
__global__ void k_dis() {
    int i = blockIdx.x * blockDim.x + threadIdx.x;
    if (i < NT) g_dis_t[i] = rsqrtf(g_dis_t[i] + 1.0f);
    if (i < NC) g_dis_c[i] = rsqrtf(g_dis_c[i] + 1.0f);
}

// ---- kM: 6x6 quadratic form M[i][j] = sum_h B_i[h] B_j[h] wlin[h] ----
__global__ void k_M(const float* __restrict__ Wt, const float* __restrict__ bt,
                    const float* __restrict__ Wc, const float* __restrict__ bc,
                    const float* __restrict__ wl) {
    __shared__ float B[6][HD];
    __shared__ float Bw[HD];
    int h = threadIdx.x;  // 128 threads
    B[0][h] = Wt[h];
    B[1][h] = bt[h];
    B[2][h] = Wc[h];
    B[3][h] = Wc[HD + h];
    B[4][h] = Wc[2 * HD + h];
    B[5][h] = bc[h];
    Bw[h] = wl[h];
    __syncthreads();
    int warp = h >> 5, lane = h & 31;
    for (int pi = warp; pi < 36; pi += 4) {
        int i = pi / 6, j = pi % 6;
        float s = 0.f;
        #pragma unroll
        for (int t = lane; t < HD; t += 32)
            s += B[i][t] * B[j][t] * Bw[t];
        #pragma unroll
        for (int o = 16; o > 0; o >>= 1)
            s += __shfl_xor_sync(0xffffffff, s, o);
        if (lane == 0) g_M[pi] = s;
    }
}

// ---- k3: edge aggregation (both graphs) ----
__global__ void k_agg(const int* __restrict__ eit,
                      const int* __restrict__ eic,
                      const float* __restrict__ ew,
                      const float* __restrict__ xcar) {
    int e = blockIdx.x * blockDim.x + threadIdx.x;
    if (e >= NE) return;
    // truck: scalar feature 1 everywhere -> aggregate norm only
    int rt = eit[e], ct = eit[NE + e];
    atomicAdd(&g_coef[ct], g_dis_t[rt] * g_dis_t[ct]);
    // car: aggregate 3-dim input features weighted by norm
    int rc = eic[e], cc = eic[NE + e];
    float norm = g_dis_c[rc] * ew[e] * g_dis_c[cc];
    atomicAdd(&g_gc[3 * cc + 0], norm * xcar[3 * rc + 0]);
    atomicAdd(&g_gc[3 * cc + 1], norm * xcar[3 * rc + 1]);
    atomicAdd(&g_gc[3 * cc + 2], norm * xcar[3 * rc + 2]);
}

// ---- k4: add self-loops, build per-node compact coefficient vectors ----
__global__ void k_u(const float* __restrict__ xcar) {
    int n = blockIdx.x * blockDim.x + threadIdx.x;
    if (n >= NT + NC) return;
    float4 u;
    if (n < NT) {
        float d = g_dis_t[n];
        u = make_float4(g_coef[n] + d * d, 1.f, 0.f, 0.f);
    } else {
        int c = n - NT;
        float d = g_dis_c[c];
        float d2 = d * d;
        u = make_float4(g_gc[3 * c + 0] + d2 * xcar[3 * c + 0],
                        g_gc[3 * c + 1] + d2 * xcar[3 * c + 1],
                        g_gc[3 * c + 2] + d2 * xcar[3 * c + 2],
                        1.f);
    }
    g_u[n] = u;
}

// ---- k5: pair scoring: score = u_s^T M u_d + b_lin ----
__global__ void k_pair(const int* __restrict__ src,
                       const int* __restrict__ dst,
                       const float* __restrict__ bl,
                       float* __restrict__ out) {
    __shared__ float M[36];
    if (threadIdx.x < 36) M[threadIdx.x] = g_M[threadIdx.x];
    __syncthreads();
    int p = blockIdx.x * blockDim.x + threadIdx.x;
    if (p >= NP) return;
    int s = src[p], d = dst[p];
    float4 us4 = g_u[s], ud4 = g_u[d];
    float us[6] = {0.f, 0.f, 0.f, 0.f, 0.f, 0.f};
    float ud[6] = {0.f, 0.f, 0.f, 0.f, 0.f, 0.f};
    if (s < NT) { us[0] = us4.x; us[1] = us4.y; }
    else        { us[2] = us4.x; us[3] = us4.y; us[4] = us4.z; us[5] = us4.w; }
    if (d < NT) { ud[0] = ud4.x; ud[1] = ud4.y; }
    else        { ud[2] = ud4.x; ud[3] = ud4.y; ud[4] = ud4.z; ud[5] = ud4.w; }
    float acc = bl[0];
    #pragma unroll
    for (int i = 0; i < 6; i++) {
        float t = 0.f;
        #pragma unroll
        for (int j = 0; j < 6; j++)
            t += M[6 * i + j] * ud[j];
        acc += us[i] * t;
    }
    out[p] = acc;
}

extern "C" void kernel_launch(void* const* d_in, const int* in_sizes, int n_in,
                              void* d_out, int out_size) {
    const float* xcar = (const float*)d_in[0];
    const int*   eit  = (const int*)d_in[1];
    const int*   eic  = (const int*)d_in[2];
    const float* ew   = (const float*)d_in[3];
    const int*   src  = (const int*)d_in[4];
    const int*   dst  = (const int*)d_in[5];
    // n_truck may or may not be materialized as input 6 (scalar). Detect:
    int w0 = (in_sizes[6] == 1) ? 7 : 6;
    const float* Wt = (const float*)d_in[w0 + 0];
    const float* bt = (const float*)d_in[w0 + 1];
    const float* Wc = (const float*)d_in[w0 + 2];
    const float* bc = (const float*)d_in[w0 + 3];
    const float* wl = (const float*)d_in[w0 + 4];
    const float* bl = (const float*)d_in[w0 + 5];
    float* out = (float*)d_out;

    const int TPB = 256;
    k_zero<<<(NC * 3 + TPB - 1) / TPB, TPB>>>();
    k_M<<<1, HD>>>(Wt, bt, Wc, bc, wl);
    k_deg<<<(NE + TPB - 1) / TPB, TPB>>>(eit, eic, ew);
    k_dis<<<(NT + TPB - 1) / TPB, TPB>>>();
    k_agg<<<(NE + TPB - 1) / TPB, TPB>>>(eit, eic, ew, xcar);
    k_u<<<(NT + NC + TPB - 1) / TPB, TPB>>>(xcar);
    k_pair<<<(NP + TPB - 1) / TPB, TPB>>>(src, dst, bl, out);
}

// round 2
// speedup vs baseline: 1.2405x; 1.2405x over previous
#include <cuda_runtime.h>

#define NT 100000
#define NC 100000
#define NE 1600000
#define NP 200000
#define HD 128

// ---- scratch (static __device__, no allocation) ----
__device__ float  g_dis_t[NT];      // truck deg -> dis
__device__ float  g_dis_c[NC];      // car deg -> dis
__device__ float  g_coef[NT];       // truck scalar aggregate
__device__ float4 g_gc4[NC];        // car 3-dim aggregate (+pad), vector-red target
__device__ float4 g_xd4[NC];        // packed (x0,x1,x2,dis_c) for single-gather
__device__ float4 g_u[NT + NC];     // per-node compact coefficients
__device__ float  g_M[36];          // 6x6 quadratic-form matrix

__device__ __forceinline__ void red_add_v4(float4* addr, float a, float b, float c, float d) {
    asm volatile("red.global.add.v4.f32 [%0], {%1,%2,%3,%4};"
                 :: "l"(addr), "f"(a), "f"(b), "f"(c), "f"(d) : "memory");
}

// ---- k0: zero scratch ----
__global__ void k_zero() {
    int i = blockIdx.x * blockDim.x + threadIdx.x;
    if (i < NT) { g_dis_t[i] = 0.f; g_coef[i] = 0.f; }
    if (i < NC) g_dis_c[i] = 0.f;
    if (i < NC * 4) ((float*)g_gc4)[i] = 0.f;
}

// ---- k1: degree accumulation, 4 edges/thread, vector loads ----
__global__ void __launch_bounds__(256) k_deg(const int* __restrict__ eit,
                                             const int* __restrict__ eic,
                                             const float* __restrict__ ew) {
    int t = blockIdx.x * blockDim.x + threadIdx.x;
    int base = t * 4;
    if (base >= NE) return;
    int4   ct4 = *(const int4*)(eit + NE + base);
    int4   cc4 = *(const int4*)(eic + NE + base);
    float4 w4  = *(const float4*)(ew + base);
    atomicAdd(&g_dis_t[ct4.x], 1.0f);
    atomicAdd(&g_dis_t[ct4.y], 1.0f);
    atomicAdd(&g_dis_t[ct4.z], 1.0f);
    atomicAdd(&g_dis_t[ct4.w], 1.0f);
    atomicAdd(&g_dis_c[cc4.x], w4.x);
    atomicAdd(&g_dis_c[cc4.y], w4.y);
    atomicAdd(&g_dis_c[cc4.z], w4.z);
    atomicAdd(&g_dis_c[cc4.w], w4.w);
}

// ---- k2: deg -> dis = rsqrt(deg + 1); pack (x, dis_c) into g_xd4 ----
__global__ void k_dis(const float* __restrict__ xcar) {
    int i = blockIdx.x * blockDim.x + threadIdx.x;
    if (i < NT) g_dis_t[i] = rsqrtf(g_dis_t[i] + 1.0f);
    if (i < NC) {
        float d = rsqrtf(g_dis_c[i] + 1.0f);
        g_dis_c[i] = d;
        g_xd4[i] = make_float4(xcar[3 * i + 0], xcar[3 * i + 1], xcar[3 * i + 2], d);
    }
}

// ---- kM: 6x6 quadratic form M[i][j] = sum_h B_i[h] B_j[h] wlin[h] ----
__global__ void k_M(const float* __restrict__ Wt, const float* __restrict__ bt,
                    const float* __restrict__ Wc, const float* __restrict__ bc,
                    const float* __restrict__ wl) {
    __shared__ float B[6][HD];
    __shared__ float Bw[HD];
    int h = threadIdx.x;  // 128 threads
    B[0][h] = Wt[h];
    B[1][h] = bt[h];
    B[2][h] = Wc[h];
    B[3][h] = Wc[HD + h];
    B[4][h] = Wc[2 * HD + h];
    B[5][h] = bc[h];
    Bw[h] = wl[h];
    __syncthreads();
    int warp = h >> 5, lane = h & 31;
    for (int pi = warp; pi < 36; pi += 4) {
        int i = pi / 6, j = pi % 6;
        float s = 0.f;
        #pragma unroll
        for (int t = lane; t < HD; t += 32)
            s += B[i][t] * B[j][t] * Bw[t];
        #pragma unroll
        for (int o = 16; o > 0; o >>= 1)
            s += __shfl_xor_sync(0xffffffff, s, o);
        if (lane == 0) g_M[pi] = s;
    }
}

// ---- k3: edge aggregation, 4 edges/thread, packed gathers + v4 reductions ----
__global__ void __launch_bounds__(256) k_agg(const int* __restrict__ eit,
                                             const int* __restrict__ eic,
                                             const float* __restrict__ ew) {
    int t = blockIdx.x * blockDim.x + threadIdx.x;
    int base = t * 4;
    if (base >= NE) return;
    int4   rt4 = *(const int4*)(eit + base);
    int4   ct4 = *(const int4*)(eit + NE + base);
    int4   rc4 = *(const int4*)(eic + base);
    int4   cc4 = *(const int4*)(eic + NE + base);
    float4 w4  = *(const float4*)(ew + base);

    int rt[4] = {rt4.x, rt4.y, rt4.z, rt4.w};
    int ct[4] = {ct4.x, ct4.y, ct4.z, ct4.w};
    int rc[4] = {rc4.x, rc4.y, rc4.z, rc4.w};
    int cc[4] = {cc4.x, cc4.y, cc4.z, cc4.w};
    float w[4] = {w4.x, w4.y, w4.z, w4.w};

    // front-batch the random gathers for MLP
    float dtr[4], dtc[4], dcc[4];
    float4 xd[4];
    #pragma unroll
    for (int k = 0; k < 4; k++) {
        dtr[k] = g_dis_t[rt[k]];
        dtc[k] = g_dis_t[ct[k]];
        dcc[k] = g_dis_c[cc[k]];
        xd[k]  = g_xd4[rc[k]];
    }
    #pragma unroll
    for (int k = 0; k < 4; k++) {
        atomicAdd(&g_coef[ct[k]], dtr[k] * dtc[k]);
        float norm = xd[k].w * w[k] * dcc[k];
        red_add_v4(&g_gc4[cc[k]], norm * xd[k].x, norm * xd[k].y, norm * xd[k].z, 0.f);
    }
}

// ---- k4: add self-loops, build per-node compact coefficient vectors ----
__global__ void k_u() {
    int n = blockIdx.x * blockDim.x + threadIdx.x;
    if (n >= NT + NC) return;
    float4 u;
    if (n < NT) {
        float d = g_dis_t[n];
        u = make_float4(g_coef[n] + d * d, 1.f, 0.f, 0.f);
    } else {
        int c = n - NT;
        float4 gc = g_gc4[c];
        float4 xd = g_xd4[c];
        float d2 = xd.w * xd.w;
        u = make_float4(gc.x + d2 * xd.x,
                        gc.y + d2 * xd.y,
                        gc.z + d2 * xd.z,
                        1.f);
    }
    g_u[n] = u;
}

// ---- k5: pair scoring: score = u_s^T M u_d + b_lin ----
__global__ void k_pair(const int* __restrict__ src,
                       const int* __restrict__ dst,
                       const float* __restrict__ bl,
                       float* __restrict__ out) {
    __shared__ float M[36];
    if (threadIdx.x < 36) M[threadIdx.x] = g_M[threadIdx.x];
    __syncthreads();
    int p = blockIdx.x * blockDim.x + threadIdx.x;
    if (p >= NP) return;
    int s = src[p], d = dst[p];
    float4 us4 = g_u[s], ud4 = g_u[d];
    float us[6] = {0.f, 0.f, 0.f, 0.f, 0.f, 0.f};
    float ud[6] = {0.f, 0.f, 0.f, 0.f, 0.f, 0.f};
    if (s < NT) { us[0] = us4.x; us[1] = us4.y; }
    else        { us[2] = us4.x; us[3] = us4.y; us[4] = us4.z; us[5] = us4.w; }
    if (d < NT) { ud[0] = ud4.x; ud[1] = ud4.y; }
    else        { ud[2] = ud4.x; ud[3] = ud4.y; ud[4] = ud4.z; ud[5] = ud4.w; }
    float acc = bl[0];
    #pragma unroll
    for (int i = 0; i < 6; i++) {
        float t = 0.f;
        #pragma unroll
        for (int j = 0; j < 6; j++)
            t += M[6 * i + j] * ud[j];
        acc += us[i] * t;
    }
    out[p] = acc;
}

extern "C" void kernel_launch(void* const* d_in, const int* in_sizes, int n_in,
                              void* d_out, int out_size) {
    const float* xcar = (const float*)d_in[0];
    const int*   eit  = (const int*)d_in[1];
    const int*   eic  = (const int*)d_in[2];
    const float* ew   = (const float*)d_in[3];
    const int*   src  = (const int*)d_in[4];
    const int*   dst  = (const int*)d_in[5];
    int w0 = (in_sizes[6] == 1) ? 7 : 6;
    const float* Wt = (const float*)d_in[w0 + 0];
    const float* bt = (const float*)d_in[w0 + 1];
    const float* Wc = (const float*)d_in[w0 + 2];
    const float* bc = (const float*)d_in[w0 + 3];
    const float* wl = (const float*)d_in[w0 + 4];
    const float* bl = (const float*)d_in[w0 + 5];
    float* out = (float*)d_out;

    const int TPB = 256;
    k_zero<<<(NC * 4 + TPB - 1) / TPB, TPB>>>();
    k_M<<<1, HD>>>(Wt, bt, Wc, bc, wl);
    k_deg<<<(NE / 4 + TPB - 1) / TPB, TPB>>>(eit, eic, ew);
    k_dis<<<(NC + TPB - 1) / TPB, TPB>>>(xcar);
    k_agg<<<(NE / 4 + TPB - 1) / TPB, TPB>>>(eit, eic, ew);
    k_u<<<(NT + NC + TPB - 1) / TPB, TPB>>>();
    k_pair<<<(NP + TPB - 1) / TPB, TPB>>>(src, dst, bl, out);
}